// round 2
// baseline (speedup 1.0000x reference)
#include <cuda_runtime.h>

#define HW    4096
#define CDIM  256
#define BATCH 32
#define NH    4
#define HID   64
#define NSEL  40
#define W1S   68   // padded smem stride (bank-conflict mitigation, 16B-aligned rows)

// Scratch (device globals: allocation-free rule)
__device__ float g_scale[BATCH * HW];
__device__ float g_imp[BATCH * HW];

__device__ __forceinline__ unsigned long long splat2(float v) {
    unsigned long long r;
    asm("mov.b64 %0, {%1, %1};" : "=l"(r) : "r"(__float_as_uint(v)));
    return r;
}
__device__ __forceinline__ void ffma2(unsigned long long& d, unsigned long long a,
                                      unsigned long long b) {
    asm("fma.rn.f32x2 %0, %1, %2, %0;" : "+l"(d) : "l"(a), "l"(b));
}

// ---------------------------------------------------------------------------
// K1: per-pixel modulator (W1:256->64 relu, W2:64->4 sigmoid, mean heads, x0.7)
//     + importance = sum_c |x|. One thread per pixel, packed f32x2 FMA.
// ---------------------------------------------------------------------------
extern __shared__ float s_w1[];  // [256][W1S], s_w1[c*W1S + o]

__global__ __launch_bounds__(256) void mod_kernel(
    const float* __restrict__ x, const float* __restrict__ w1,
    const float* __restrict__ b1, const float* __restrict__ w2,
    const float* __restrict__ b2)
{
    __shared__ float s_w2[NH * HID];
    __shared__ float s_b1[HID];
    __shared__ float s_b2[NH];
    int tid = threadIdx.x;

    // Load + transpose W1: w1[o*256+c] -> s_w1[c*W1S+o]
    for (int i = tid; i < HID * CDIM; i += 256) {
        int o = i >> 8, c = i & 255;
        s_w1[c * W1S + o] = w1[i];
    }
    for (int i = tid; i < NH * HID; i += 256) s_w2[i] = w2[i];
    if (tid < HID) s_b1[tid] = b1[tid];
    if (tid < NH)  s_b2[tid] = b2[tid];
    __syncthreads();

    int b = blockIdx.x >> 4;                       // 16 tiles of 256 px per batch
    int p = ((blockIdx.x & 15) << 8) + tid;
    const float* xp = x + (size_t)b * CDIM * HW + p;

    unsigned long long acc[HID / 2];
#pragma unroll
    for (int j = 0; j < HID / 2; ++j) acc[j] = 0ull;
    float aimp = 0.f;

#pragma unroll 4
    for (int c = 0; c < CDIM; ++c) {
        float xv = __ldg(xp + (size_t)c * HW);     // coalesced 128B/warp
        aimp += fabsf(xv);
        unsigned long long xx = splat2(xv);
        const unsigned long long* wr =
            reinterpret_cast<const unsigned long long*>(s_w1 + c * W1S);
#pragma unroll
        for (int j = 0; j < HID / 2; ++j) ffma2(acc[j], xx, wr[j]);
    }

    float h1[HID];
#pragma unroll
    for (int j = 0; j < HID / 2; ++j) {
        unsigned int lo, hi;
        asm("mov.b64 {%0, %1}, %2;" : "=r"(lo), "=r"(hi) : "l"(acc[j]));
        h1[2 * j]     = fmaxf(__uint_as_float(lo) + s_b1[2 * j], 0.f);
        h1[2 * j + 1] = fmaxf(__uint_as_float(hi) + s_b1[2 * j + 1], 0.f);
    }

    float msum = 0.f;
#pragma unroll
    for (int o = 0; o < NH; ++o) {
        float z = s_b2[o];
#pragma unroll
        for (int j = 0; j < HID; ++j) z = fmaf(s_w2[o * HID + j], h1[j], z);
        msum += 1.f / (1.f + expf(-z));
    }

    int idx = b * HW + p;
    g_scale[idx] = 0.7f * 0.25f * msum;   // 0.7 * mean over 4 heads
    g_imp[idx]   = aimp;                  // ranking invariant to /256
}

// ---------------------------------------------------------------------------
// K2: per-batch top-40 by importance; add 0.3 * (1/40) = 0.0075 to selected.
//     (softmax rows sum to 1 => graph pixel importance == 1/NSEL exactly)
// ---------------------------------------------------------------------------
__global__ __launch_bounds__(256) void topk_kernel()
{
    __shared__ float sv[HW];
    __shared__ float rv[256];
    __shared__ int   ri[256];
    int b = blockIdx.x, tid = threadIdx.x;

    for (int i = tid; i < HW; i += 256) sv[i] = g_imp[b * HW + i];
    __syncthreads();

    for (int it = 0; it < NSEL; ++it) {
        float best = -1e30f; int bi = 0;
        for (int i = tid; i < HW; i += 256) {
            float v = sv[i];
            if (v > best) { best = v; bi = i; }   // first-found => lowest idx on tie
        }
        rv[tid] = best; ri[tid] = bi;
        __syncthreads();
        for (int s = 128; s > 0; s >>= 1) {
            if (tid < s) {
                float v2 = rv[tid + s]; int i2 = ri[tid + s];
                if (v2 > rv[tid] || (v2 == rv[tid] && i2 < ri[tid])) {
                    rv[tid] = v2; ri[tid] = i2;
                }
            }
            __syncthreads();
        }
        if (tid == 0) {
            int w = ri[0];
            sv[w] = -1e30f;
            g_scale[b * HW + w] += 0.3f * (1.0f / (float)NSEL);
        }
        __syncthreads();
    }
}

// ---------------------------------------------------------------------------
// K3: out = x * scale[b,p], float4 vectorized.
// ---------------------------------------------------------------------------
__global__ __launch_bounds__(256) void apply_kernel(const float* __restrict__ x,
                                                    float* __restrict__ out)
{
    int f = blockIdx.x * blockDim.x + threadIdx.x;   // float4 index, 8388608 total
    int base = f << 2;
    int b = base >> 20;          // C*HW = 2^20
    int p = base & (HW - 1);
    float4 xv = __ldg(reinterpret_cast<const float4*>(x) + f);
    float4 sv = *reinterpret_cast<const float4*>(&g_scale[(b << 12) + p]);
    float4 ov;
    ov.x = xv.x * sv.x; ov.y = xv.y * sv.y;
    ov.z = xv.z * sv.z; ov.w = xv.w * sv.w;
    reinterpret_cast<float4*>(out)[f] = ov;
}

// ---------------------------------------------------------------------------
extern "C" void kernel_launch(void* const* d_in, const int* in_sizes, int n_in,
                              void* d_out, int out_size)
{
    const float* x  = (const float*)d_in[0];
    const float* w1 = (const float*)d_in[1];
    const float* b1 = (const float*)d_in[2];
    const float* w2 = (const float*)d_in[3];
    const float* b2 = (const float*)d_in[4];
    float* out = (float*)d_out;

    const int smem = CDIM * W1S * (int)sizeof(float);  // 69632 B
    (void)cudaFuncSetAttribute(mod_kernel,
                               cudaFuncAttributeMaxDynamicSharedMemorySize, smem);

    mod_kernel<<<BATCH * (HW / 256), 256, smem>>>(x, w1, b1, w2, b2);
    topk_kernel<<<BATCH, 256>>>();
    apply_kernel<<<(BATCH * CDIM * HW / 4) / 256, 256>>>(x, out);
}

// round 5
// speedup vs baseline: 1.8587x; 1.8587x over previous
#include <cuda_runtime.h>

#define HW    4096
#define CDIM  256
#define BATCH 32
#define NH    4
#define HID   64
#define NSEL  40
#define KC    16
#define BM    128

// Scratch (device globals: allocation-free rule)
__device__ float g_scale[BATCH * HW];
__device__ float g_imp[BATCH * HW];
__device__ float g_w1t[CDIM * HID];   // W1 transposed: [c][o]

__device__ __forceinline__ unsigned long long splat2(float v) {
    unsigned long long r;
    asm("mov.b64 %0, {%1, %1};" : "=l"(r) : "r"(__float_as_uint(v)));
    return r;
}
__device__ __forceinline__ void ffma2(unsigned long long& d, unsigned long long a,
                                      unsigned long long b) {
    asm("fma.rn.f32x2 %0, %1, %2, %0;" : "+l"(d) : "l"(a), "l"(b));
}

// ---------------------------------------------------------------------------
// K0: transpose W1 [o][c] -> [c][o] so tile loads are coalesced.
// ---------------------------------------------------------------------------
__global__ void transpose_w1(const float* __restrict__ w1) {
    int i = blockIdx.x * 256 + threadIdx.x;   // 16384 elems
    int o = i >> 8, c = i & 255;
    g_w1t[c * HID + o] = w1[i];
}

// ---------------------------------------------------------------------------
// K1: register-tiled GEMM [128px x 64hid x 256k] per block + fused importance.
//     Pixels packed in f32x2 pairs -> a-operand read straight from smem as u64.
// ---------------------------------------------------------------------------
// Dynamic smem layout (floats):
//   sA   [2][KC][BM]   @ 0      (4096)
//   sB   [2][KC][HID]  @ 4096   (2048)
//   sImp [8][BM]       @ 6144   (1024)
//   sH1  [BM][65]      @ 7168   (8320)
//   sW2  [256]         @ 15488
//   sB1  [64]          @ 15744
//   sB2  [4]           @ 15808   -> total 15812 floats = 63248 B
#define SM_A    0
#define SM_B    4096
#define SM_IMP  6144
#define SM_H1   7168
#define SM_W2   15488
#define SM_B1   15744
#define SM_B2   15808
#define SM_TOT  15812

extern __shared__ float sm[];

__global__ __launch_bounds__(256, 3) void mod_kernel(
    const float* __restrict__ x, const float* __restrict__ b1,
    const float* __restrict__ w2, const float* __restrict__ b2)
{
    const int tid = threadIdx.x;
    const int b   = blockIdx.x >> 5;          // 32 tiles per batch
    const int p0  = (blockIdx.x & 31) << 7;   // 128 px per tile
    const float* xb = x + (size_t)b * CDIM * HW + p0;

    // small weights
    sm[SM_W2 + tid] = w2[tid];
    if (tid < HID) sm[SM_B1 + tid] = b1[tid];
    if (tid < NH)  sm[SM_B2 + tid] = b2[tid];

    // loader mapping
    const int lc  = tid >> 5;                 // 0..7  (c rows, +8 for second)
    const int lp4 = (tid & 31) << 2;          // pixel group of 4
    const int bc  = tid >> 4;                 // 0..15 (w rows)
    const int bo4 = (tid & 15) << 2;          // hid group of 4
    // compute mapping
    const int tx = tid & 15;                  // hid group: o = tx*4..+3
    const int ty = tid >> 4;                  // px group:  p = ty*8..+7

    unsigned long long acc[4][4];
#pragma unroll
    for (int j = 0; j < 4; ++j)
#pragma unroll
        for (int o = 0; o < 4; ++o) acc[j][o] = 0ull;
    float imp4[4] = {0.f, 0.f, 0.f, 0.f};

    float4 ra0, ra1, rb;

    // prologue: chunk 0
    ra0 = *(const float4*)(xb + (size_t)lc * HW + lp4);
    ra1 = *(const float4*)(xb + (size_t)(lc + 8) * HW + lp4);
    rb  = *(const float4*)(g_w1t + bc * HID + bo4);
    *(float4*)(sm + SM_A + lc * BM + lp4)        = ra0;
    *(float4*)(sm + SM_A + (lc + 8) * BM + lp4)  = ra1;
    *(float4*)(sm + SM_B + bc * HID + bo4)       = rb;
    imp4[0] += fabsf(ra0.x) + fabsf(ra1.x);
    imp4[1] += fabsf(ra0.y) + fabsf(ra1.y);
    imp4[2] += fabsf(ra0.z) + fabsf(ra1.z);
    imp4[3] += fabsf(ra0.w) + fabsf(ra1.w);
    __syncthreads();

    int buf = 0;
#pragma unroll 1
    for (int ch = 0; ch < CDIM / KC; ++ch) {
        if (ch < CDIM / KC - 1) {             // prefetch next chunk (LDG overlaps compute)
            int c0 = (ch + 1) * KC;
            ra0 = *(const float4*)(xb + (size_t)(c0 + lc) * HW + lp4);
            ra1 = *(const float4*)(xb + (size_t)(c0 + lc + 8) * HW + lp4);
            rb  = *(const float4*)(g_w1t + (c0 + bc) * HID + bo4);
        }
        const float* A = sm + SM_A + buf * (KC * BM) + (ty << 3);
        const float* B = sm + SM_B + buf * (KC * HID) + (tx << 2);
#pragma unroll
        for (int k = 0; k < KC; ++k) {
            ulonglong2 av0 = *(const ulonglong2*)(A + k * BM);
            ulonglong2 av1 = *(const ulonglong2*)(A + k * BM + 4);
            float4 bv = *(const float4*)(B + k * HID);
            unsigned long long bs0 = splat2(bv.x), bs1 = splat2(bv.y);
            unsigned long long bs2 = splat2(bv.z), bs3 = splat2(bv.w);
            ffma2(acc[0][0], av0.x, bs0); ffma2(acc[0][1], av0.x, bs1);
            ffma2(acc[0][2], av0.x, bs2); ffma2(acc[0][3], av0.x, bs3);
            ffma2(acc[1][0], av0.y, bs0); ffma2(acc[1][1], av0.y, bs1);
            ffma2(acc[1][2], av0.y, bs2); ffma2(acc[1][3], av0.y, bs3);
            ffma2(acc[2][0], av1.x, bs0); ffma2(acc[2][1], av1.x, bs1);
            ffma2(acc[2][2], av1.x, bs2); ffma2(acc[2][3], av1.x, bs3);
            ffma2(acc[3][0], av1.y, bs0); ffma2(acc[3][1], av1.y, bs1);
            ffma2(acc[3][2], av1.y, bs2); ffma2(acc[3][3], av1.y, bs3);
        }
        if (ch < CDIM / KC - 1) {
            __syncthreads();
            buf ^= 1;
            *(float4*)(sm + SM_A + buf * (KC * BM) + lc * BM + lp4)       = ra0;
            *(float4*)(sm + SM_A + buf * (KC * BM) + (lc + 8) * BM + lp4) = ra1;
            *(float4*)(sm + SM_B + buf * (KC * HID) + bc * HID + bo4)     = rb;
            imp4[0] += fabsf(ra0.x) + fabsf(ra1.x);
            imp4[1] += fabsf(ra0.y) + fabsf(ra1.y);
            imp4[2] += fabsf(ra0.z) + fabsf(ra1.z);
            imp4[3] += fabsf(ra0.w) + fabsf(ra1.w);
            __syncthreads();
        }
    }

    // importance partials (deterministic reduction, no float atomics)
    *(float4*)(sm + SM_IMP + lc * BM + lp4) = make_float4(imp4[0], imp4[1], imp4[2], imp4[3]);

    __syncthreads();

    // h1 = relu(acc + b1) -> smem [px][65]
#pragma unroll
    for (int j = 0; j < 4; ++j) {
#pragma unroll
        for (int oo = 0; oo < 4; ++oo) {
            unsigned int lo, hi;
            asm("mov.b64 {%0, %1}, %2;" : "=r"(lo), "=r"(hi) : "l"(acc[j][oo]));
            int o = (tx << 2) + oo;
            int pe = (ty << 3) + (j << 1);
            float bo = sm[SM_B1 + o];
            sm[SM_H1 + pe * 65 + o]       = fmaxf(__uint_as_float(lo) + bo, 0.f);
            sm[SM_H1 + (pe + 1) * 65 + o] = fmaxf(__uint_as_float(hi) + bo, 0.f);
        }
    }
    __syncthreads();

    if (tid < BM) {
        // finalize importance
        float s = 0.f;
#pragma unroll
        for (int l = 0; l < 8; ++l) s += sm[SM_IMP + l * BM + tid];
        g_imp[b * HW + p0 + tid] = s;
        // second layer + sigmoid mean
        const float* h1 = sm + SM_H1 + tid * 65;
        float msum = 0.f;
#pragma unroll
        for (int o = 0; o < NH; ++o) {
            float z = sm[SM_B2 + o];
#pragma unroll
            for (int j = 0; j < HID; ++j) z = fmaf(sm[SM_W2 + o * HID + j], h1[j], z);
            msum += 1.f / (1.f + expf(-z));
        }
        g_scale[b * HW + p0 + tid] = 0.7f * 0.25f * msum;
    }
}

// ---------------------------------------------------------------------------
// K2: per-batch top-40 tournament; add 0.3/40 to selected pixels.
//     (softmax rows sum to 1 => graph pixel importance == 1/NSEL exactly)
// ---------------------------------------------------------------------------
__global__ __launch_bounds__(1024) void topk_kernel()
{
    __shared__ unsigned long long sW[32];
    __shared__ unsigned long long sBest;
    const int b = blockIdx.x, tid = threadIdx.x;
    const int base = tid << 2;

    float4 v4 = *(const float4*)(g_imp + b * HW + base);
    float v[4] = {v4.x, v4.y, v4.z, v4.w};   // strictly positive sums of |x|

    for (int it = 0; it < NSEL; ++it) {
        unsigned long long k = 0ull;
#pragma unroll
        for (int j = 0; j < 4; ++j) {
            unsigned long long kj =
                ((unsigned long long)__float_as_uint(v[j]) << 32) |
                (unsigned)(HW - 1 - (base + j));   // tie -> lower idx wins
            k = (kj > k) ? kj : k;
        }
#pragma unroll
        for (int s = 16; s; s >>= 1) {
            unsigned long long o = __shfl_xor_sync(0xffffffffu, k, s);
            k = (o > k) ? o : k;
        }
        if ((tid & 31) == 0) sW[tid >> 5] = k;
        __syncthreads();
        if (tid < 32) {
            unsigned long long kk = sW[tid];
#pragma unroll
            for (int s = 16; s; s >>= 1) {
                unsigned long long o = __shfl_xor_sync(0xffffffffu, kk, s);
                kk = (o > kk) ? o : kk;
            }
            if (tid == 0) sBest = kk;
        }
        __syncthreads();
        int idx = (HW - 1) - (int)(unsigned)(sBest & 0xffffffffu);
        if ((idx >> 2) == tid) {
            v[idx & 3] = 0.0f;
            g_scale[b * HW + idx] += 0.3f / (float)NSEL;
        }
    }
}

// ---------------------------------------------------------------------------
// K3: out = x * scale[b,p], float4 vectorized.
// ---------------------------------------------------------------------------
__global__ __launch_bounds__(256) void apply_kernel(const float* __restrict__ x,
                                                    float* __restrict__ out)
{
    int f = blockIdx.x * blockDim.x + threadIdx.x;   // float4 index
    int base = f << 2;
    int b = base >> 20;                              // C*HW = 2^20
    int p = base & (HW - 1);
    float4 xv = __ldg(reinterpret_cast<const float4*>(x) + f);
    float4 sv = *reinterpret_cast<const float4*>(&g_scale[(b << 12) + p]);
    float4 ov;
    ov.x = xv.x * sv.x; ov.y = xv.y * sv.y;
    ov.z = xv.z * sv.z; ov.w = xv.w * sv.w;
    reinterpret_cast<float4*>(out)[f] = ov;
}

// ---------------------------------------------------------------------------
extern "C" void kernel_launch(void* const* d_in, const int* in_sizes, int n_in,
                              void* d_out, int out_size)
{
    const float* x  = (const float*)d_in[0];
    const float* w1 = (const float*)d_in[1];
    const float* b1 = (const float*)d_in[2];
    const float* w2 = (const float*)d_in[3];
    const float* b2 = (const float*)d_in[4];
    float* out = (float*)d_out;

    const int smem = SM_TOT * (int)sizeof(float);   // 63248 B
    (void)cudaFuncSetAttribute(mod_kernel,
                               cudaFuncAttributeMaxDynamicSharedMemorySize, smem);

    transpose_w1<<<64, 256>>>(w1);
    mod_kernel<<<BATCH * (HW / BM), 256, smem>>>(x, b1, w2, b2);
    topk_kernel<<<BATCH, 1024>>>();
    apply_kernel<<<(BATCH * CDIM * HW / 4) / 256, 256>>>(x, out);
}